// round 13
// baseline (speedup 1.0000x reference)
#include <cuda_runtime.h>
#include <math.h>

typedef unsigned long long u64;
typedef unsigned int u32;
typedef unsigned short u16;

#define BI 8
#define PP 2000
#define NC 81
#define CPP 80
#define CAP 16384
#define KPRE 2048
#define DET 100
#define NBIN 8192
#define BINSHIFT 50   // key>>50 == float bits [31:18]; sign==0 for scores>0
#define MAXN 256
#define W_IMGF 1333.0f
#define H_IMGF 800.0f
#define SCORE_T 0.05f
#define NMS_T 0.5f
#define XFORM_CLIP 4.135166556742356f

// ---------------- device scratch (zero-initialized at load) ----------------
__device__ int g_cnt[BI];
__device__ u64 g_keys[BI][CAP];      // raw candidates from gen
__device__ u64 g_bnd[BI][CAP];       // boundary staging + fallback scratch
__device__ u64 g_ckeys[BI][KPRE];    // selected keys grouped by class (unsorted)
__device__ int g_classoff[BI][CPP];
__device__ int g_classcnt[BI][CPP];
__device__ u64 g_kept[BI][KPRE];     // NMS survivors' keys (unordered)
__device__ u64 g_unk[BI][KPRE];      // suppressed keys (unordered)
__device__ int g_kc[BI];
__device__ int g_uc[BI];
__device__ int g_done_nms[BI];

// ---------------- helpers ----------------
__device__ __forceinline__ float4 decode_clip(float4 pr, float4 rel) {
    float w = pr.z - pr.x;
    float h = pr.w - pr.y;
    float cx = pr.x + 0.5f * w;
    float cy = pr.y + 0.5f * h;
    float dx = rel.x / 10.0f;
    float dy = rel.y / 10.0f;
    float dw = fminf(rel.z / 5.0f, XFORM_CLIP);
    float dh = fminf(rel.w / 5.0f, XFORM_CLIP);
    float pcx = dx * w + cx;
    float pcy = dy * h + cy;
    float pw = expf(dw) * w;
    float ph = expf(dh) * h;
    float x1 = fminf(fmaxf(pcx - 0.5f * pw, 0.0f), W_IMGF);
    float y1 = fminf(fmaxf(pcy - 0.5f * ph, 0.0f), H_IMGF);
    float x2 = fminf(fmaxf(pcx + 0.5f * pw, 0.0f), W_IMGF);
    float y2 = fminf(fmaxf(pcy + 0.5f * ph, 0.0f), H_IMGF);
    return make_float4(x1, y1, x2, y2);
}

__device__ __forceinline__ float4 decode_from_idx(u32 idx, int b,
                                                  const float* __restrict__ boxreg,
                                                  const float* __restrict__ props) {
    int p = idx / CPP;
    int cm1 = idx - p * CPP;
    int gw = b * PP + p;
    float4 pr = reinterpret_cast<const float4*>(props)[gw];
    float4 rel = reinterpret_cast<const float4*>(boxreg)[(long long)gw * NC + cm1 + 1];
    return decode_clip(pr, rel);
}

__device__ __forceinline__ u64 sel_mm(u64 v, u64 o, bool takeMax) {
    return takeMax ? (v > o ? v : o) : (v < o ? v : o);
}

__device__ __forceinline__ bool iou_gt(float4 bi, float ai, float4 be, float ae) {
    float lx = fmaxf(bi.x, be.x), ly = fmaxf(bi.y, be.y);
    float rx = fminf(bi.z, be.z), ry = fminf(bi.w, be.w);
    float iw = fmaxf(rx - lx, 0.f), ih = fmaxf(ry - ly, 0.f);
    float inter = iw * ih;
    float uni = ai + ae - inter;
    return inter / fmaxf(uni, 1e-9f) > NMS_T;
}

// warp-collective sort of 64 u64 keys held as (r0 at x=lane, r1 at x=lane+32);
// up=true => descending block.
__device__ __forceinline__ void wsort64(u64& r0, u64& r1, int lane, bool up) {
    #pragma unroll
    for (int k2 = 2; k2 <= 32; k2 <<= 1) {
        #pragma unroll
        for (int j = k2 >> 1; j; j >>= 1) {
            {
                int x = lane;
                u64 o = __shfl_xor_sync(0xffffffffu, r0, j);
                r0 = sel_mm(r0, o, ((x & k2) == 0) == ((x & j) == 0));
            }
            {
                int x = lane + 32;
                u64 o = __shfl_xor_sync(0xffffffffu, r1, j);
                r1 = sel_mm(r1, o, ((x & k2) == 0) == ((x & j) == 0));
            }
        }
    }
    u64 lo = (r0 < r1) ? r0 : r1;
    u64 hi = (r0 < r1) ? r1 : r0;
    r0 = up ? hi : lo;
    r1 = up ? lo : hi;
    #pragma unroll
    for (int j = 16; j; j >>= 1) {
        bool tkm = up == ((lane & j) == 0);
        u64 o0 = __shfl_xor_sync(0xffffffffu, r0, j);
        u64 o1 = __shfl_xor_sync(0xffffffffu, r1, j);
        r0 = sel_mm(r0, o0, tkm);
        r1 = sel_mm(r1, o1, tkm);
    }
}

// descending bitonic sort of M (pow2, 128..2048) keys in smem, 256 threads.
__device__ void bsort_desc_256(u64* a, int M, int tid, int lane, int wid) {
    for (int blk = wid; blk < M / 64; blk += 8) {
        u64 r0 = a[blk * 64 + lane];
        u64 r1 = a[blk * 64 + lane + 32];
        wsort64(r0, r1, lane, (blk & 1) == 0);
        a[blk * 64 + lane] = r0;
        a[blk * 64 + lane + 32] = r1;
    }
    __syncthreads();
    for (int k2 = 128; k2 <= M; k2 <<= 1) {
        for (int j = k2 >> 1; j >= 64; j >>= 1) {
            for (int pp = tid; pp < M / 2; pp += 256) {
                int i = ((pp & ~(j - 1)) << 1) | (pp & (j - 1));
                u64 x = a[i], y = a[i + j];
                bool up = ((i & k2) == 0);
                if ((x < y) == up) { a[i] = y; a[i + j] = x; }
            }
            __syncthreads();
        }
        for (int blk = wid; blk < M / 64; blk += 8) {
            int base = blk * 64;
            bool up = ((base & k2) == 0);
            u64 r0 = a[base + lane];
            u64 r1 = a[base + lane + 32];
            u64 lo = (r0 < r1) ? r0 : r1;
            u64 hi = (r0 < r1) ? r1 : r0;
            r0 = up ? hi : lo;
            r1 = up ? lo : hi;
            #pragma unroll
            for (int j = 16; j; j >>= 1) {
                bool tkm = up == ((lane & j) == 0);
                u64 o0 = __shfl_xor_sync(0xffffffffu, r0, j);
                u64 o1 = __shfl_xor_sync(0xffffffffu, r1, j);
                r0 = sel_mm(r0, o0, tkm);
                r1 = sel_mm(r1, o1, tkm);
            }
            a[base + lane] = r0;
            a[base + lane + 32] = r1;
        }
        __syncthreads();
    }
}

// sort skeys[0..n) desc (pad zeros to M), using 256 threads.
__device__ void sort_desc_any(u64* skeys, int n, int tid, int lane, int wid) {
    int M = 64;
    while (M < n) M <<= 1;
    for (int e = n + tid; e < M; e += 256) skeys[e] = 0ull;
    __syncthreads();
    if (M == 64) {
        if (wid == 0) {
            u64 r0 = skeys[lane];
            u64 r1 = skeys[lane + 32];
            wsort64(r0, r1, lane, true);
            skeys[lane] = r0;
            skeys[lane + 32] = r1;
        }
    } else {
        bsort_desc_256(skeys, M, tid, lane, wid);
    }
    __syncthreads();
}

// ================= K1: softmax + candidate gen =================
__global__ void k_gen(const float* __restrict__ logits,
                      const float* __restrict__ boxreg,
                      const float* __restrict__ props) {
    int gw = (blockIdx.x * blockDim.x + threadIdx.x) >> 5;
    int lane = threadIdx.x & 31;
    if (gw >= BI * PP) return;
    int b = gw / PP;
    int p = gw - b * PP;

    const float* lrow = logits + (long long)gw * NC;
    float l0 = lrow[lane];
    float l1 = lrow[lane + 32];
    float l2 = (lane + 64 < NC) ? lrow[lane + 64] : -1e30f;

    float m = fmaxf(l0, fmaxf(l1, l2));
    #pragma unroll
    for (int o = 16; o; o >>= 1) m = fmaxf(m, __shfl_xor_sync(0xffffffffu, m, o));
    float e0 = __expf(l0 - m);
    float e1 = __expf(l1 - m);
    float e2 = (lane + 64 < NC) ? __expf(l2 - m) : 0.0f;
    float s = e0 + e1 + e2;
    #pragma unroll
    for (int o = 16; o; o >>= 1) s += __shfl_xor_sync(0xffffffffu, s, o);
    float thresh = SCORE_T * s;

    float4 pr = reinterpret_cast<const float4*>(props)[gw];

    bool ok[3];
    float sc[3];
    #pragma unroll
    for (int r = 0; r < 3; r++) {
        int ci = lane + r * 32;
        float e = (r == 0) ? e0 : ((r == 1) ? e1 : e2);
        ok[r] = false;
        sc[r] = 0.0f;
        if (ci >= 1 && ci < NC && e > thresh) {
            float4 rel = reinterpret_cast<const float4*>(boxreg)[(long long)gw * NC + ci];
            float4 bx = decode_clip(pr, rel);
            if ((bx.z - bx.x) >= 0.01f && (bx.w - bx.y) >= 0.01f) {
                ok[r] = true;
                sc[r] = e / s;
            }
        }
    }

    unsigned bal[3];
    bal[0] = __ballot_sync(0xffffffffu, ok[0]);
    bal[1] = __ballot_sync(0xffffffffu, ok[1]);
    bal[2] = __ballot_sync(0xffffffffu, ok[2]);
    int cnt0 = __popc(bal[0]);
    int cnt1 = __popc(bal[1]);
    int tot = cnt0 + cnt1 + __popc(bal[2]);
    int base = 0;
    if (lane == 0 && tot) base = atomicAdd(&g_cnt[b], tot);
    base = __shfl_sync(0xffffffffu, base, 0);

    unsigned below = (1u << lane) - 1u;
    #pragma unroll
    for (int r = 0; r < 3; r++) {
        if (ok[r]) {
            int off = __popc(bal[r] & below) + ((r > 0) ? cnt0 : 0) + ((r > 1) ? cnt1 : 0);
            int slot = base + off;
            if (slot < CAP) {
                unsigned idx = (unsigned)(p * CPP + (lane + r * 32 - 1));
                g_keys[b][slot] = ((u64)__float_as_uint(sc[r]) << 32) |
                                  (u64)(0xFFFFFFFFu - idx);
            }
        }
    }
}

// ================= K2: select top-2048 SET + class grouping (no sort) =====
__global__ void __launch_bounds__(1024, 1)
k_select() {
    extern __shared__ char smc[];
    u64* acc = (u64*)smc;                       // 2048 u64 (16KB)
    int* hist = (int*)(smc + 16384);            // 8192 int (32KB)
    u64* bnd = (u64*)(smc + 16384);             // overlay: up to 2048 u64

    __shared__ int s_t, s_A, s_R, aCtr, bCtr, wsum[32];
    __shared__ int classcnt[CPP], classoff_s[CPP], classfill[CPP];

    const int tid = threadIdx.x;
    const int lane = tid & 31;
    const int wid = tid >> 5;
    const int b = blockIdx.x;
    const int cnt = min(g_cnt[b], CAP);
    const int K = min(cnt, KPRE);

    // A1: histogram on float bits [30:18]
    for (int i = tid; i < NBIN; i += 1024) hist[i] = 0;
    if (tid == 0) { s_t = 0x7FFFFFFF; s_A = 0; s_R = 0; aCtr = 0; bCtr = 0; }
    __syncthreads();
    for (int base = 0; base < cnt; base += 1024) {
        int i = base + tid;
        int bin = (i < cnt) ? (int)(g_keys[b][i] >> BINSHIFT) : -1;
        unsigned mask = __match_any_sync(0xffffffffu, bin);
        if (bin >= 0 && lane == (__ffs(mask) - 1))
            atomicAdd(&hist[bin], __popc(mask));
    }
    __syncthreads();

    // A2: descending scan over bins, find rank-K crossing bin
    {
        const int BPT = NBIN / 1024;
        int localsum = 0;
        int bhi = NBIN - 1 - BPT * tid;
        #pragma unroll
        for (int j = 0; j < BPT; j++) localsum += hist[bhi - j];
        int v = localsum;
        #pragma unroll
        for (int o = 1; o < 32; o <<= 1) {
            int n = __shfl_up_sync(0xffffffffu, v, o);
            if (lane >= o) v += n;
        }
        if (lane == 31) wsum[wid] = v;
        __syncthreads();
        if (wid == 0) {
            int w = wsum[lane];
            #pragma unroll
            for (int o = 1; o < 32; o <<= 1) {
                int n = __shfl_up_sync(0xffffffffu, w, o);
                if (lane >= o) w += n;
            }
            wsum[lane] = w;
        }
        __syncthreads();
        int incl = v + ((wid > 0) ? wsum[wid - 1] : 0);
        int excl = incl - localsum;
        if (K > 0 && excl < K && K <= incl) {
            int run = excl;
            for (int j = 0; j < BPT; j++) {
                int bin = bhi - j;
                int h = hist[bin];
                if (run < K && K <= run + h) { s_t = bin; s_A = run; s_R = K - run; }
                run += h;
            }
        }
    }
    __syncthreads();
    const int tbin = s_t, A = s_A, R = s_R;
    __syncthreads();   // hist dead; bnd overlays it

    // A3: compact above-bin keys to acc (unordered); boundary bin -> g_bnd
    for (int base = 0; base < cnt; base += 1024) {
        int i = base + tid;
        u64 key = (i < cnt) ? g_keys[b][i] : 0ull;
        int bin = (i < cnt) ? (int)(key >> BINSHIFT) : -1;
        bool above = bin > tbin;
        bool atb = bin == tbin;
        unsigned balA = __ballot_sync(0xffffffffu, above);
        unsigned balB = __ballot_sync(0xffffffffu, atb);
        int bA = 0, bB = 0;
        if (lane == 0) {
            if (balA) bA = atomicAdd(&aCtr, __popc(balA));
            if (balB) bB = atomicAdd(&bCtr, __popc(balB));
        }
        bA = __shfl_sync(0xffffffffu, bA, 0);
        bB = __shfl_sync(0xffffffffu, bB, 0);
        unsigned below = (1u << lane) - 1u;
        if (above) acc[bA + __popc(balA & below)] = key;
        else if (atb) g_bnd[b][bB + __popc(balB & below)] = key;
    }
    __syncthreads();

    // A4: boundary bin -> its top R (desc) appended at acc[A..K)
    int m = bCtr;
    if (m > 0) {
        if (m <= 64) {
            if (wid == 0) {
                u64 r0 = (lane < m) ? g_bnd[b][lane] : 0ull;
                u64 r1 = (lane + 32 < m) ? g_bnd[b][lane + 32] : 0ull;
                wsort64(r0, r1, lane, true);
                if (lane < R) acc[A + lane] = r0;
                if (lane + 32 < R) acc[A + lane + 32] = r1;
            }
        } else {
            int M = 1;
            while (M < m) M <<= 1;
            if (M <= 2048) {
                for (int i = tid; i < M; i += 1024) bnd[i] = (i < m) ? g_bnd[b][i] : 0ull;
                __syncthreads();
                for (int k2 = 2; k2 <= M; k2 <<= 1) {
                    for (int j = k2 >> 1; j; j >>= 1) {
                        for (int i = tid; i < M; i += 1024) {
                            int ixj = i ^ j;
                            if (ixj > i) {
                                u64 a = bnd[i], c = bnd[ixj];
                                bool up = ((i & k2) == 0);
                                if ((a < c) == up) { bnd[i] = c; bnd[ixj] = a; }
                            }
                        }
                        __syncthreads();
                    }
                }
                for (int i = tid; i < R; i += 1024) acc[A + i] = bnd[i];
            } else {
                // gmem bitonic fallback (practically never)
                for (int i = m + tid; i < M; i += 1024) g_bnd[b][i] = 0ull;
                __syncthreads();
                for (int k2 = 2; k2 <= M; k2 <<= 1) {
                    for (int j = k2 >> 1; j; j >>= 1) {
                        for (int i = tid; i < M; i += 1024) {
                            int ixj = i ^ j;
                            if (ixj > i) {
                                u64 a = g_bnd[b][i], c = g_bnd[b][ixj];
                                bool up = ((i & k2) == 0);
                                if ((a < c) == up) { g_bnd[b][i] = c; g_bnd[b][ixj] = a; }
                            }
                        }
                        __syncthreads();
                    }
                }
                for (int i = tid; i < R; i += 1024) acc[A + i] = g_bnd[b][i];
            }
        }
    }
    if (tid < CPP) { classcnt[tid] = 0; classfill[tid] = 0; }
    __syncthreads();

    // B: per-class counts (aggregated), scan, scatter (unordered within class)
    for (int i = tid; i < KPRE; i += 1024) {
        bool valid = i < K;
        u64 key = valid ? acc[i] : 0ull;
        u32 L = valid ? ((0xFFFFFFFFu - (u32)key) % CPP) : 0xFFFFFFFFu;
        unsigned mask = __match_any_sync(0xffffffffu, L);
        if (valid && lane == (__ffs(mask) - 1))
            atomicAdd(&classcnt[L], __popc(mask));
    }
    __syncthreads();
    if (tid < CPP) g_classcnt[b][tid] = classcnt[tid];
    {
        int v = 0;
        if (tid < 96) {
            v = (tid < CPP) ? classcnt[tid] : 0;
            #pragma unroll
            for (int o = 1; o < 32; o <<= 1) {
                int n = __shfl_up_sync(0xffffffffu, v, o);
                if (lane >= o) v += n;
            }
            if (lane == 31) wsum[wid] = v;
        }
        __syncthreads();
        if (tid < CPP) {
            int add = 0;
            for (int w = 0; w < wid; w++) add += wsum[w];
            int off = v + add - classcnt[tid];
            classoff_s[tid] = off;
            g_classoff[b][tid] = off;
        }
    }
    __syncthreads();
    for (int i = tid; i < KPRE; i += 1024) {
        bool valid = i < K;
        u64 key = valid ? acc[i] : 0ull;
        u32 L = valid ? ((0xFFFFFFFFu - (u32)key) % CPP) : 0xFFFFFFFFu;
        unsigned mask = __match_any_sync(0xffffffffu, L);
        int leader = __ffs(mask) - 1;
        int base = 0;
        if (valid && lane == leader) base = atomicAdd(&classfill[L], __popc(mask));
        base = __shfl_sync(0xffffffffu, base, leader);
        if (valid) {
            int rank = __popc(mask & ((1u << lane) - 1u));
            g_ckeys[b][classoff_s[L] + base + rank] = key;
        }
    }

    if (tid == 0) g_cnt[b] = 0;   // reset for next graph replay
}

// ================= K3: per-class sort + NMS + fused output =================
__global__ void __launch_bounds__(256)
k_nms_out(const float* __restrict__ boxreg,
          const float* __restrict__ props,
          float* __restrict__ out) {
    extern __shared__ char smn[];
    u64* skeys = (u64*)smn;                     // 2048 u64 (16KB)
    float4* sbox = (float4*)(smn + 16384);      // 256 float4 (4KB)
    float* sarea = (float*)(smn + 20480);       // 256 float (1KB)
    u64* smask = (u64*)(smn + 21504);           // 256*4 u64 (8KB)

    __shared__ u64 skept[4];
    __shared__ u64 finalk[DET];
    __shared__ int sdone;

    const int cls = blockIdx.x;
    const int b = blockIdx.y;
    const int tid = threadIdx.x;
    const int lane = tid & 31;
    const int wid = tid >> 5;
    const int n = g_classcnt[b][cls];
    const int off = g_classoff[b][cls];
    const unsigned full = 0xffffffffu;

    if (n > 0) {
        for (int e = tid; e < n; e += 256) skeys[e] = g_ckeys[b][off + e];
        __syncthreads();
        sort_desc_any(skeys, n, tid, lane, wid);   // visiting order = key desc

        unsigned char* kflag = (unsigned char*)(&g_bnd[b][0]) + off;  // fallback only

        if (n <= MAXN) {
            // decode class boxes (parallel)
            {
                int e = tid;
                if (e < n) {
                    u32 idx = 0xFFFFFFFFu - (u32)skeys[e];
                    float4 bx = decode_from_idx(idx, b, boxreg, props);
                    sbox[e] = bx;
                    sarea[e] = fmaxf(bx.z - bx.x, 0.f) * fmaxf(bx.w - bx.y, 0.f);
                }
            }
            __syncthreads();
            // parallel suppression-mask build
            const int NW = (n + 63) >> 6;
            for (int i = wid; i < n; i += 8) {
                float4 bi = sbox[i];
                float ai = sarea[i];
                for (int w = 0; w < NW; w++) {
                    int j0 = w * 64 + lane;
                    int j1 = j0 + 32;
                    bool s0 = (j0 > i && j0 < n) && iou_gt(bi, ai, sbox[j0], sarea[j0]);
                    bool s1 = (j1 > i && j1 < n) && iou_gt(bi, ai, sbox[j1], sarea[j1]);
                    unsigned m0 = __ballot_sync(full, s0);
                    unsigned m1 = __ballot_sync(full, s1);
                    if (lane == 0) smask[i * NW + w] = (u64)m0 | ((u64)m1 << 32);
                }
            }
            __syncthreads();
            if (tid == 0) {
                u64 k0 = ~0ull, k1 = ~0ull, k2 = ~0ull, k3 = ~0ull;
                for (int i = 0; i < n; i++) {
                    int w = i >> 6;
                    u64 kw = (w == 0) ? k0 : ((w == 1) ? k1 : ((w == 2) ? k2 : k3));
                    if ((kw >> (i & 63)) & 1ull) {
                        const u64* row = &smask[i * NW];
                        k0 &= ~row[0];
                        if (NW > 1) k1 &= ~row[1];
                        if (NW > 2) k2 &= ~row[2];
                        if (NW > 3) k3 &= ~row[3];
                    }
                }
                skept[0] = k0; skept[1] = k1; skept[2] = k2; skept[3] = k3;
            }
            __syncthreads();
        } else {
            // fallback (never in practice): serial greedy with on-the-fly decode
            if (tid == 0) {
                for (int e = 0; e < n; e++) kflag[e] = 1;
                for (int i = 0; i < n; i++) {
                    if (!kflag[i]) continue;
                    u32 idx = 0xFFFFFFFFu - (u32)skeys[i];
                    float4 bi = decode_from_idx(idx, b, boxreg, props);
                    float ai = fmaxf(bi.z - bi.x, 0.f) * fmaxf(bi.w - bi.y, 0.f);
                    for (int e = i + 1; e < n; e++) {
                        if (!kflag[e]) continue;
                        u32 idxe = 0xFFFFFFFFu - (u32)skeys[e];
                        float4 be = decode_from_idx(idxe, b, boxreg, props);
                        float ae = fmaxf(be.z - be.x, 0.f) * fmaxf(be.w - be.y, 0.f);
                        if (iou_gt(bi, ai, be, ae)) kflag[e] = 0;
                    }
                }
            }
            __syncthreads();
        }

        // partition kept/unkept keys into per-image buffers (order irrelevant)
        for (int e0 = 0; e0 < n; e0 += 256) {
            int e = e0 + tid;
            bool valid = e < n;
            bool kp = valid && ((n <= MAXN)
                          ? ((skept[e >> 6] >> (e & 63)) & 1ull)
                          : (kflag[e] != 0));
            unsigned bk = __ballot_sync(full, kp);
            unsigned bu = __ballot_sync(full, valid && !kp);
            int basek = 0, baseu = 0;
            if (lane == 0) {
                if (bk) basek = atomicAdd(&g_kc[b], __popc(bk));
                if (bu) baseu = atomicAdd(&g_uc[b], __popc(bu));
            }
            basek = __shfl_sync(full, basek, 0);
            baseu = __shfl_sync(full, baseu, 0);
            unsigned below = (1u << lane) - 1u;
            if (kp) g_kept[b][basek + __popc(bk & below)] = skeys[e];
            else if (valid) g_unk[b][baseu + __popc(bu & below)] = skeys[e];
        }
    }

    // ---- last-block-done: 80th block for image b emits output ----
    __threadfence();
    __syncthreads();
    if (tid == 0) sdone = atomicAdd(&g_done_nms[b], 1);
    __syncthreads();
    if (sdone != CPP - 1) return;
    __threadfence();

    const int kc = min(g_kc[b], KPRE);
    const int uc = min(g_uc[b], KPRE);

    // sort kept keys desc; final order = kept desc, then unkept desc.
    for (int e = tid; e < kc; e += 256) skeys[e] = g_kept[b][e];
    __syncthreads();
    sort_desc_any(skeys, kc, tid, lane, wid);
    if (tid < DET && tid < kc) finalk[tid] = skeys[tid];
    if (kc < DET) {
        __syncthreads();
        for (int e = tid; e < uc; e += 256) skeys[e] = g_unk[b][e];
        __syncthreads();
        sort_desc_any(skeys, uc, tid, lane, wid);
        if (tid < DET && tid >= kc && (tid - kc) < uc) finalk[tid] = skeys[tid - kc];
        if (tid < DET && tid >= kc + uc) finalk[tid] = 0ull;
    }
    __syncthreads();

    if (tid < DET) {
        u64 key = finalk[tid];
        bool kp = tid < kc;
        bool real = tid < kc + uc;
        float4 bx = make_float4(0.f, 0.f, 0.f, 0.f);
        float label = 1.0f;
        float sc = -1.0f;
        if (real) {
            u32 idx = 0xFFFFFFFFu - (u32)key;
            bx = decode_from_idx(idx, b, boxreg, props);
            label = (float)(idx % CPP + 1);
            if (kp) sc = __uint_as_float((u32)(key >> 32));
        }
        out[(b * DET + tid) * 4 + 0] = bx.x;
        out[(b * DET + tid) * 4 + 1] = bx.y;
        out[(b * DET + tid) * 4 + 2] = bx.z;
        out[(b * DET + tid) * 4 + 3] = bx.w;
        out[BI * DET * 4 + b * DET + tid] = sc;
        out[BI * DET * 5 + b * DET + tid] = label;
        out[BI * DET * 6 + b * DET + tid] = kp ? 1.0f : 0.0f;
    }
    if (tid == 0) {
        g_kc[b] = 0;
        g_uc[b] = 0;
        g_done_nms[b] = 0;
    }
}

// ---------------- launch ----------------
extern "C" void kernel_launch(void* const* d_in, const int* in_sizes, int n_in,
                              void* d_out, int out_size) {
    const float* logits = (const float*)d_in[0];
    const float* boxreg = (const float*)d_in[1];
    const float* props  = (const float*)d_in[2];
    float* out = (float*)d_out;

    cudaFuncSetAttribute(k_select, cudaFuncAttributeMaxDynamicSharedMemorySize, 49152);
    cudaFuncSetAttribute(k_nms_out, cudaFuncAttributeMaxDynamicSharedMemorySize, 29696);

    k_gen<<<(BI * PP * 32 + 255) / 256, 256>>>(logits, boxreg, props);
    k_select<<<BI, 1024, 49152>>>();
    k_nms_out<<<dim3(CPP, BI), 256, 29696>>>(boxreg, props, out);
}